// round 6
// baseline (speedup 1.0000x reference)
#include <cuda_runtime.h>

#define BATCH   2
#define CF      64
#define NXD     468
#define NYD     468
#define GRID    (NXD * NYD)      // 219024
#define NP_PER  60000
#define HRD     48
#define WRD     512
#define RSP     (HRD * WRD)      // 24576
#define TCELL   64               // cells per gather tile (last tile has 16)
#define NTILES  ((GRID + TCELL - 1) / TCELL)   // 3423

// Winner-index maps: [0 .. B*G) spatial, [B*G .. 2*B*G) bev. -1 = empty.
__device__ __align__(16) int g_win[2 * BATCH * GRID];
// Channel-last transposed range_out: [B][RSP][64]
__device__ __align__(16) float g_rot[BATCH * RSP * CF];

#define SCAT_BLOCKS 625          // ceil(160000/256)
#define TRANS_BLOCKS (RSP / 32 * (CF / 32) * BATCH)   // 3072

// Fused prologue: blocks [0,625) scatter winners; blocks [625,3697) transpose
// range_out. Last-write-wins == highest point index (serial XLA scatter order).
// XLA's arcp rewrite makes v/0.16f == v*6.25f exactly (verified rel_err==0.0).
__global__ void __launch_bounds__(256) k_prologue(
        const int* __restrict__ vc, const float* __restrict__ lp,
        const float* __restrict__ ro, int n_pillar, int n_laser) {
    if (blockIdx.x < SCAT_BLOCKS) {
        int i = blockIdx.x * 256 + threadIdx.x;
        if (i < n_pillar) {
            int b   = vc[i * 4 + 0];
            int lin = vc[i * 4 + 1] + vc[i * 4 + 2] * NXD + vc[i * 4 + 3];
            if (b < 0 || b >= BATCH || lin < 0 || lin >= GRID) return;
            atomicMax(&g_win[b * GRID + lin], i);
        } else {
            int p = i - n_pillar;
            if (p >= n_laser) return;
            float x = lp[p * 5 + 1];
            float y = lp[p * 5 + 2];
            bool valid = (x > 0.0f) && (x < 69.12f) && (y > -39.68f) && (y < 39.68f)
                      && (x >= 0.0f) && (x < 468.0f) && (y >= 0.0f) && (y < 468.0f);
            if (!valid) return;
            int xi = (int)__fmul_rn(-y, 6.25f) + 248;   // XOFF
            int yi = (int)__fmul_rn(-x, 6.25f) + 432;   // YOFF
            xi = min(max(xi, 0), 495);
            yi = min(max(yi, 0), 431);
            if (xi >= NXD) return;                      // mode='drop'
            int b = p / NP_PER;
            atomicMax(&g_win[BATCH * GRID + b * GRID + yi * NXD + xi], p);
        }
    } else {
        // Transpose range_out (B,64,RSP) -> g_rot (B,RSP,64), 32x32 tiles.
        __shared__ float tile[32][33];
        int j  = blockIdx.x - SCAT_BLOCKS;
        int s0 = (j % (RSP / 32)) * 32;
        int c0 = ((j / (RSP / 32)) % (CF / 32)) * 32;
        int b  = j / (RSP / 32 * (CF / 32));
        int tx = threadIdx.x & 31, ty = threadIdx.x >> 5;   // (32, 8)
        #pragma unroll
        for (int k = 0; k < 4; k++) {
            int c = c0 + ty + k * 8;
            tile[ty + k * 8][tx] = ro[((size_t)(b * CF + c)) * RSP + s0 + tx];
        }
        __syncthreads();
        #pragma unroll
        for (int k = 0; k < 4; k++) {
            int s = s0 + ty + k * 8;
            g_rot[((size_t)(b * RSP + s)) * CF + c0 + tx] = tile[tx][ty + k * 8];
        }
    }
}

// Tiled gather: one block = 64 cells x 128 channels (32 KB of output).
// Latency-hiding: 8 independent float4 gathers in flight per thread in
// phase 1; 2 barriers per 32 KB of output. smem [ch][cell] keeps phase 1
// STS stride-1 and phase 2 a single LDS.128 + STG.128 per vector.
// __stcs output stores keep the 26 MB read working set L2-resident.
__global__ void __launch_bounds__(256) k_gather(
        const float* __restrict__ pf,
        const int*   __restrict__ lx,
        const int*   __restrict__ ly,
        const float* __restrict__ lp,
        float*       __restrict__ out) {
    __shared__ float s_val[128][TCELL];    // 32 KB: [ch][cell]
    __shared__ float s_zc[TCELL];
    __shared__ int   s_off[TCELL];
    __shared__ int   s_wiS[TCELL];

    int tile = blockIdx.x;
    int b    = blockIdx.y;
    int t    = threadIdx.x;
    int cell0  = tile * TCELL;
    int ncells = min(TCELL, GRID - cell0);

    if (t < TCELL) {
        int wiS = -1, wiB = -1;
        if (t < ncells) {
            wiS = g_win[b * GRID + cell0 + t];
            wiB = g_win[BATCH * GRID + b * GRID + cell0 + t];
        }
        s_wiS[t] = wiS;
        float zc = 0.0f; int off = -1;
        if (wiB >= 0) {
            float z = lp[wiB * 5 + 3];
            zc  = fminf(fmaxf(z, -2.0f), 4.0f);
            off = b * RSP + ly[wiB * 2 + 1] * WRD + lx[wiB * 2 + 1];
        }
        s_zc[t] = zc; s_off[t] = off;
    }
    __syncthreads();

    // Phase 1: 1024 items per half (cell = i&63, v = i>>6 in 0..15).
    // 4 iterations x 2 gathers = 8 independent loads in flight per thread.
    #pragma unroll
    for (int it = 0; it < 4; it++) {
        int i = t + it * 256;
        int cell = i & 63;
        int v    = i >> 6;
        int wi = s_wiS[cell];
        float4 a = make_float4(0.f, 0.f, 0.f, 0.f);
        if (wi >= 0) a = *(const float4*)&pf[(size_t)wi * CF + v * 4];
        s_val[v * 4 + 0][cell] = a.x;
        s_val[v * 4 + 1][cell] = a.y;
        s_val[v * 4 + 2][cell] = a.z;
        s_val[v * 4 + 3][cell] = a.w;

        int off = s_off[cell];
        float4 r = make_float4(0.f, 0.f, 0.f, 0.f);
        if (off >= 0) {
            float zc = s_zc[cell];
            r = *(const float4*)&g_rot[(size_t)off * CF + v * 4];
            r.x = __fmul_rn(zc, r.x); r.y = __fmul_rn(zc, r.y);
            r.z = __fmul_rn(zc, r.z); r.w = __fmul_rn(zc, r.w);
        }
        s_val[CF + v * 4 + 0][cell] = r.x;
        s_val[CF + v * 4 + 1][cell] = r.y;
        s_val[CF + v * 4 + 2][cell] = r.z;
        s_val[CF + v * 4 + 3][cell] = r.w;
    }
    __syncthreads();

    // Phase 2: 2048 (LDS.128 -> STG.128) pairs; per warp 2 channels x 256B
    // contiguous runs per iteration.
    size_t base = (size_t)b * 128 * GRID + (size_t)cell0;
    #pragma unroll
    for (int it = 0; it < 8; it++) {
        int s  = t + it * 256;
        int ch = s >> 4;
        int cv = s & 15;
        if (cv * 4 < ncells) {
            float4 o = *(const float4*)&s_val[ch][cv * 4];
            __stcs((float4*)&out[base + (size_t)ch * GRID + cv * 4], o);
        }
    }
}

extern "C" void kernel_launch(void* const* d_in, const int* in_sizes, int n_in,
                              void* d_out, int out_size) {
    const float* pf = (const float*)d_in[0];   // pillar_features (B*P_PER, 64)
    const int*   vc = (const int*)  d_in[1];   // voxel_coords    (B*P_PER, 4)
    const float* ro = (const float*)d_in[2];   // range_out       (B, 64, 48, 512)
    const int*   lx = (const int*)  d_in[3];   // laser_x         (B*NP, 2)
    const int*   ly = (const int*)  d_in[4];   // laser_y         (B*NP, 2)
    const float* lp = (const float*)d_in[5];   // laser_points    (B*NP, 5)
    float* out = (float*)d_out;

    int n_pillar = in_sizes[1] / 4;
    int n_laser  = in_sizes[5] / 5;

    void* winp = nullptr;
    cudaGetSymbolAddress(&winp, g_win);
    cudaMemsetAsync(winp, 0xFF, sizeof(int) * 2 * BATCH * GRID, 0);  // all -1

    k_prologue<<<SCAT_BLOCKS + TRANS_BLOCKS, 256>>>(vc, lp, ro, n_pillar, n_laser);

    dim3 gg(NTILES, BATCH);                    // (3423, 2)
    k_gather<<<gg, 256>>>(pf, lx, ly, lp, out);
}

// round 7
// speedup vs baseline: 1.0925x; 1.0925x over previous
#include <cuda_runtime.h>

#define BATCH   2
#define CF      64
#define NXD     468
#define NYD     468
#define GRID    (NXD * NYD)      // 219024
#define NP_PER  60000
#define HRD     48
#define WRD     512
#define RSP     (HRD * WRD)      // 24576
#define TCELL   64               // cells per gather tile (last tile has 16)
#define NTILES  ((GRID + TCELL - 1) / TCELL)   // 3423

// Winner-index maps: [0 .. B*G) spatial, [B*G .. 2*B*G) bev. -1 = empty.
__device__ __align__(16) int g_win[2 * BATCH * GRID];
// Channel-last transposed range_out: [B][RSP][64]
__device__ __align__(16) float g_rot[BATCH * RSP * CF];

#define SCAT_BLOCKS 625          // ceil(160000/256)
#define TRANS_BLOCKS (RSP / 32 * (CF / 32) * BATCH)   // 3072

// Fused prologue: blocks [0,625) scatter winners; blocks [625,3697) transpose
// range_out. Last-write-wins == highest point index (serial XLA scatter order).
// XLA's arcp rewrite makes v/0.16f == v*6.25f exactly (verified rel_err==0.0).
__global__ void __launch_bounds__(256) k_prologue(
        const int* __restrict__ vc, const float* __restrict__ lp,
        const float* __restrict__ ro, int n_pillar, int n_laser) {
    if (blockIdx.x < SCAT_BLOCKS) {
        int i = blockIdx.x * 256 + threadIdx.x;
        if (i < n_pillar) {
            int b   = vc[i * 4 + 0];
            int lin = vc[i * 4 + 1] + vc[i * 4 + 2] * NXD + vc[i * 4 + 3];
            if (b < 0 || b >= BATCH || lin < 0 || lin >= GRID) return;
            atomicMax(&g_win[b * GRID + lin], i);
        } else {
            int p = i - n_pillar;
            if (p >= n_laser) return;
            float x = lp[p * 5 + 1];
            float y = lp[p * 5 + 2];
            bool valid = (x > 0.0f) && (x < 69.12f) && (y > -39.68f) && (y < 39.68f)
                      && (x >= 0.0f) && (x < 468.0f) && (y >= 0.0f) && (y < 468.0f);
            if (!valid) return;
            int xi = (int)__fmul_rn(-y, 6.25f) + 248;   // XOFF
            int yi = (int)__fmul_rn(-x, 6.25f) + 432;   // YOFF
            xi = min(max(xi, 0), 495);
            yi = min(max(yi, 0), 431);
            if (xi >= NXD) return;                      // mode='drop'
            int b = p / NP_PER;
            atomicMax(&g_win[BATCH * GRID + b * GRID + yi * NXD + xi], p);
        }
    } else {
        // Transpose range_out (B,64,RSP) -> g_rot (B,RSP,64), 32x32 tiles.
        __shared__ float tile[32][33];
        int j  = blockIdx.x - SCAT_BLOCKS;
        int s0 = (j % (RSP / 32)) * 32;
        int c0 = ((j / (RSP / 32)) % (CF / 32)) * 32;
        int b  = j / (RSP / 32 * (CF / 32));
        int tx = threadIdx.x & 31, ty = threadIdx.x >> 5;   // (32, 8)
        #pragma unroll
        for (int k = 0; k < 4; k++) {
            int c = c0 + ty + k * 8;
            tile[ty + k * 8][tx] = ro[((size_t)(b * CF + c)) * RSP + s0 + tx];
        }
        __syncthreads();
        #pragma unroll
        for (int k = 0; k < 4; k++) {
            int s = s0 + ty + k * 8;
            g_rot[((size_t)(b * RSP + s)) * CF + c0 + tx] = tile[tx][ty + k * 8];
        }
    }
}

// Pipelined tiled gather: one block = 64 cells x 128 channels, processed as
// 4 chunks of 32 channels (8 KB). While chunk c streams smem -> DRAM, chunk
// c+1's global gathers are already in flight into registers -> load and
// store pipes stay concurrently busy instead of alternating.
// Thread t owns cell = t&63: item t = spatial quad js = t>>6, item t+256 =
// bev quad js. smem [ch][cell]: STS stride-1, LDS.128 reads, conflict-free.
__global__ void __launch_bounds__(256) k_gather(
        const float* __restrict__ pf,
        const int*   __restrict__ lx,
        const int*   __restrict__ ly,
        const float* __restrict__ lp,
        float*       __restrict__ out) {
    __shared__ float s_val[32][TCELL];     // 8 KB chunk buffer [ch_local][cell]
    __shared__ float s_zc[TCELL];
    __shared__ int   s_off[TCELL];
    __shared__ int   s_wiS[TCELL];

    int tile = blockIdx.x;
    int b    = blockIdx.y;
    int t    = threadIdx.x;
    int cell0  = tile * TCELL;
    int ncells = min(TCELL, GRID - cell0);

    if (t < TCELL) {
        int wiS = -1, wiB = -1;
        if (t < ncells) {
            wiS = g_win[b * GRID + cell0 + t];
            wiB = g_win[BATCH * GRID + b * GRID + cell0 + t];
        }
        s_wiS[t] = wiS;
        float zc = 0.0f; int off = -1;
        if (wiB >= 0) {
            float z = lp[wiB * 5 + 3];
            zc  = fminf(fmaxf(z, -2.0f), 4.0f);
            off = b * RSP + ly[wiB * 2 + 1] * WRD + lx[wiB * 2 + 1];
        }
        s_zc[t] = zc; s_off[t] = off;
    }
    __syncthreads();

    int cell = t & 63;
    int js   = t >> 6;                     // 0..3: which float4 quad of chunk
    int wi   = s_wiS[cell];
    int off  = s_off[cell];
    float zc = s_zc[cell];

    float4 a, r;
    // Prefetch chunk 0.
    {
        a = make_float4(0.f, 0.f, 0.f, 0.f);
        if (wi >= 0) a = *(const float4*)&pf[(size_t)wi * CF + js * 4];
        r = make_float4(0.f, 0.f, 0.f, 0.f);
        if (off >= 0) {
            r = *(const float4*)&g_rot[(size_t)off * CF + js * 4];
            r.x = __fmul_rn(zc, r.x); r.y = __fmul_rn(zc, r.y);
            r.z = __fmul_rn(zc, r.z); r.w = __fmul_rn(zc, r.w);
        }
    }

    size_t base = (size_t)b * 128 * GRID + (size_t)cell0;
    #pragma unroll
    for (int c = 0; c < 4; c++) {
        __syncthreads();                   // chunk buffer free
        // Commit prefetched regs to smem.
        s_val[js * 4 + 0][cell] = a.x;
        s_val[js * 4 + 1][cell] = a.y;
        s_val[js * 4 + 2][cell] = a.z;
        s_val[js * 4 + 3][cell] = a.w;
        s_val[16 + js * 4 + 0][cell] = r.x;
        s_val[16 + js * 4 + 1][cell] = r.y;
        s_val[16 + js * 4 + 2][cell] = r.z;
        s_val[16 + js * 4 + 3][cell] = r.w;
        // Issue chunk c+1 gathers now; latency hides under the store phase.
        if (c < 3) {
            int v = (c + 1) * 4 + js;
            a = make_float4(0.f, 0.f, 0.f, 0.f);
            if (wi >= 0) a = *(const float4*)&pf[(size_t)wi * CF + v * 4];
            r = make_float4(0.f, 0.f, 0.f, 0.f);
            if (off >= 0) {
                r = *(const float4*)&g_rot[(size_t)off * CF + v * 4];
                r.x = __fmul_rn(zc, r.x); r.y = __fmul_rn(zc, r.y);
                r.z = __fmul_rn(zc, r.z); r.w = __fmul_rn(zc, r.w);
            }
        }
        __syncthreads();                   // chunk buffer filled
        // Stream chunk c: 512 vectors (32 ch x 16 cell-quads), 2 per thread.
        #pragma unroll
        for (int it = 0; it < 2; it++) {
            int s  = t + it * 256;
            int cl = s >> 4;               // ch_local 0..31
            int cv = s & 15;
            if (cv * 4 < ncells) {
                int ch = (cl < 16) ? (c * 16 + cl) : (48 + c * 16 + cl);
                float4 o = *(const float4*)&s_val[cl][cv * 4];
                __stcs((float4*)&out[base + (size_t)ch * GRID + cv * 4], o);
            }
        }
    }
}

extern "C" void kernel_launch(void* const* d_in, const int* in_sizes, int n_in,
                              void* d_out, int out_size) {
    const float* pf = (const float*)d_in[0];   // pillar_features (B*P_PER, 64)
    const int*   vc = (const int*)  d_in[1];   // voxel_coords    (B*P_PER, 4)
    const float* ro = (const float*)d_in[2];   // range_out       (B, 64, 48, 512)
    const int*   lx = (const int*)  d_in[3];   // laser_x         (B*NP, 2)
    const int*   ly = (const int*)  d_in[4];   // laser_y         (B*NP, 2)
    const float* lp = (const float*)d_in[5];   // laser_points    (B*NP, 5)
    float* out = (float*)d_out;

    int n_pillar = in_sizes[1] / 4;
    int n_laser  = in_sizes[5] / 5;

    void* winp = nullptr;
    cudaGetSymbolAddress(&winp, g_win);
    cudaMemsetAsync(winp, 0xFF, sizeof(int) * 2 * BATCH * GRID, 0);  // all -1

    k_prologue<<<SCAT_BLOCKS + TRANS_BLOCKS, 256>>>(vc, lp, ro, n_pillar, n_laser);

    dim3 gg(NTILES, BATCH);                    // (3423, 2)
    k_gather<<<gg, 256>>>(pf, lx, ly, lp, out);
}